// round 14
// baseline (speedup 1.0000x reference)
#include <cuda_runtime.h>
#include <cuda_bf16.h>
#include <cstdint>
#include <cstddef>

// Output row: [obj(1) | cls(80) | reg(64) | box(4)] = 149 cols, rows = B*8400
#define OUT_COLS   149
#define ROWS_PER_B 8400
#define NT         256

#define TILE_M 128
#define TILE_K 64              // fp32 k per stage
#define NSTG   4               // 256 / 64

// smem layout (bytes). A tile: [64 k][256B = 128 m bf16]; W tile: [80 n][128B = 64 k bf16]
#define SM_BIAS   0            // 80 floats
#define BUF_BASE  1024
#define OFF_AH    0
#define OFF_AL    16384
#define OFF_WH    32768
#define OFF_WL    43008
#define BUF_SZ    53248
#define SMEM_TOTAL (BUF_BASE + 2 * BUF_SZ)   // 107520

// SW128 swizzle for 128B rows (W tile)
#define SWZ(off) ((off) ^ (((off) >> 3) & 0x70))
// A tile swizzle: 256B rows, 16B chunk index XOR'd with (k & 7)
__device__ __forceinline__ uint32_t aswz(int krow, int mbyte) {
    return (uint32_t)krow * 256 + ((((mbyte >> 4) ^ (krow & 7)) & 15) << 4) + (mbyte & 15);
}

__device__ __forceinline__ uint32_t smem_u32(const void* p) {
    return (uint32_t)__cvta_generic_to_shared(p);
}

#define LDSM4T(r, a)                                                            \
    asm volatile("ldmatrix.sync.aligned.m8n8.x4.trans.shared.b16 "              \
                 "{%0,%1,%2,%3}, [%4];"                                         \
                 : "=r"((r)[0]), "=r"((r)[1]), "=r"((r)[2]), "=r"((r)[3])       \
                 : "r"(a))

#define LDSM2(r, a)                                                             \
    asm volatile("ldmatrix.sync.aligned.m8n8.x2.shared.b16 {%0,%1}, [%2];"      \
                 : "=r"((r)[0]), "=r"((r)[1]) : "r"(a))

#define MMA16816(c, A_, B_)                                                     \
    asm volatile("mma.sync.aligned.m16n8k16.row.col.f32.bf16.bf16.f32 "         \
                 "{%0,%1,%2,%3}, {%4,%5,%6,%7}, {%8,%9}, {%0,%1,%2,%3};"        \
                 : "+f"((c)[0]), "+f"((c)[1]), "+f"((c)[2]), "+f"((c)[3])       \
                 : "r"((A_)[0]), "r"((A_)[1]), "r"((A_)[2]), "r"((A_)[3]),      \
                   "r"((B_)[0]), "r"((B_)[1]))

// ---- truncation-based bf16 split (exact hi/lo decomposition) ----
// hi = top 16 bits of fp32 (truncated bf16); lo = a - hi (exact in fp32), rounded to bf16.
__device__ __forceinline__ uint32_t trunc_split2(float a, float b, uint32_t& lo_pack) {
    const uint32_t ua = __float_as_uint(a);
    const uint32_t ub = __float_as_uint(b);
    uint32_t hi;
    asm("prmt.b32 %0, %1, %2, 0x7632;" : "=r"(hi) : "r"(ua), "r"(ub));
    const float fa = __uint_as_float(ua & 0xFFFF0000u);
    const float fb = __uint_as_float(ub & 0xFFFF0000u);
    const float la = a - fa;
    const float lb = b - fb;
    uint32_t lo;
    asm("cvt.rn.bf16x2.f32 %0, %1, %2;" : "=r"(lo) : "f"(lb), "f"(la));  // {hi16:lb, lo16:la}
    lo_pack = lo;
    return hi;
}

struct LvlP { const float* feat; const float* w_a; const float* w_b;
              const float* ba;   const float* bb; };
struct AllP { LvlP p[2][3]; };   // [type][level]: type 0=cls, 1=obj+reg

// Pre-converted weights: [type][level][n=80][k=256] bf16 hi/lo (static device scratch)
__device__ __align__(16) unsigned short g_preWH[2][3][80][256];
__device__ __align__(16) unsigned short g_preWL[2][3][80][256];

// One-shot weight conversion: 6 blocks (type*3+level) x 256 threads.
__global__ void wconv_kernel(AllP ap)
{
    const int type  = blockIdx.x / 3;
    const int level = blockIdx.x % 3;
    const LvlP pr = ap.p[type][level];
    for (int idx = threadIdx.x; idx < 80 * 256; idx += NT) {
        const int o = idx >> 8;
        const int k = idx & 255;
        float w = 0.0f;
        if (type == 0)   w = pr.w_a[(size_t)o * 256 + k];
        else if (o == 0) w = pr.w_a[k];
        else if (o < 65) w = pr.w_b[(size_t)(o - 1) * 256 + k];
        const uint32_t uw = __float_as_uint(w);
        const unsigned short h = (unsigned short)(uw >> 16);
        const float lo = w - __uint_as_float(uw & 0xFFFF0000u);
        g_preWH[type][level][o][k] = h;
        g_preWL[type][level][o][k] = __bfloat16_as_ushort(__float2bfloat16(lo));
    }
}

__global__ __launch_bounds__(NT, 2)
void hmma_kernel(AllP ap, float* __restrict__ out)
{
    extern __shared__ char smem[];
    const uint32_t sbase = smem_u32(smem);
    const int tid  = threadIdx.x;
    const int wid  = tid >> 5;
    const int lane = tid & 31;
    const int warp_m = wid >> 1;      // 0..3 -> m rows warp_m*32
    const int warp_n = wid & 1;       // 0..1 -> n cols warp_n*40

    // decode (level, tile) from blockIdx.x: tiles {50, 13, 4}
    const int bx = blockIdx.x, b = blockIdx.y, type = blockIdx.z;
    int level, tile;
    if (bx < 50)      { level = 0; tile = bx; }
    else if (bx < 63) { level = 1; tile = bx - 50; }
    else              { level = 2; tile = bx - 63; }
    const int M    = (level == 0) ? 6400 : (level == 1 ? 1600 : 400);
    const int moff = (level == 0) ? 0    : (level == 1 ? 6400 : 8000);
    const int m_base = tile * TILE_M;

    const LvlP pr = ap.p[type][level];
    const float* A = pr.feat + (size_t)b * 256 * M;
    const unsigned short* WHg = &g_preWH[type][level][0][0];
    const unsigned short* WLg = &g_preWL[type][level][0][0];

    float* biasS = (float*)(smem + SM_BIAS);
    if (tid < 80) {
        float bv;
        if (type == 0) bv = pr.ba[tid];
        else bv = (tid == 0) ? pr.ba[0] : (tid < 65 ? pr.bb[tid - 1] : 0.0f);
        biasS[tid] = bv;
    }

    // ---- stage fill ----
    auto fill = [&](int s, int buf) {
        const int k0 = s * TILE_K;
        char* bb_ = smem + BUF_BASE + buf * BUF_SZ;
        // A: [k][m] 256B rows, LDG.128 coalesced on m, trunc-split convert, STS conflict-free
#pragma unroll
        for (int i = 0; i < 8; i++) {
            const int task = tid + i * NT;       // 0..2047
            const int krow = task >> 5;          // 0..63
            const int m0   = (task & 31) * 4;    // 0..124
            const float* src = A + (size_t)(k0 + krow) * M + m_base + m0;
            float4 v;
            if (m_base + m0 + 3 < M) {
                v = *reinterpret_cast<const float4*>(src);
            } else {
                v.x = (m_base + m0 + 0 < M) ? src[0] : 0.0f;
                v.y = (m_base + m0 + 1 < M) ? src[1] : 0.0f;
                v.z = (m_base + m0 + 2 < M) ? src[2] : 0.0f;
                v.w = (m_base + m0 + 3 < M) ? src[3] : 0.0f;
            }
            uint32_t lo0, hi0 = trunc_split2(v.x, v.y, lo0);
            uint32_t lo1, hi1 = trunc_split2(v.z, v.w, lo1);
            const uint32_t off = aswz(krow, m0 * 2);   // +4 stays in same 16B chunk
            *reinterpret_cast<uint32_t*>(bb_ + OFF_AH + off)     = hi0;
            *reinterpret_cast<uint32_t*>(bb_ + OFF_AH + off + 4) = hi1;
            *reinterpret_cast<uint32_t*>(bb_ + OFF_AL + off)     = lo0;
            *reinterpret_cast<uint32_t*>(bb_ + OFF_AL + off + 4) = lo1;
        }
        // W: pure 16B copies from pre-converted global (L2-resident), SW128 dst.
        // 80 o x 8 chunks = 640 per hi/lo -> 1280 tasks, 5/thread.
#pragma unroll
        for (int i = 0; i < 5; i++) {
            const int task = tid + i * NT;       // 0..1279
            const int isLo = task >= 640;
            const int id   = isLo ? task - 640 : task;
            const int o = id >> 3;
            const int c = id & 7;                // 16B chunk within 128B row
            const unsigned short* srcp = (isLo ? WLg : WHg) + (size_t)o * 256 + k0 + c * 8;
            const uint4 v = *reinterpret_cast<const uint4*>(srcp);
            const uint32_t off = SWZ((uint32_t)o * 128 + (uint32_t)c * 16);
            *reinterpret_cast<uint4*>(bb_ + (isLo ? OFF_WL : OFF_WH) + off) = v;
        }
    };

    float acc[2][5][4];
#pragma unroll
    for (int mi = 0; mi < 2; mi++)
#pragma unroll
        for (int ni = 0; ni < 5; ni++)
#pragma unroll
            for (int r = 0; r < 4; r++) acc[mi][ni][r] = 0.0f;

    const int l7  = lane & 7;
    const int l8  = (lane >> 3) & 1;
    const int l16 = (lane >> 4) & 1;

    fill(0, 0);
    __syncthreads();

    for (int t = 0; t < NSTG; t++) {
        if (t + 1 < NSTG) fill(t + 1, (t + 1) & 1);   // other buffer; LDG latency overlaps MMAs

        const uint32_t bb_ = sbase + BUF_BASE + (t & 1) * BUF_SZ;
        const uint32_t Ah = bb_ + OFF_AH, Al = bb_ + OFF_AL;
        const uint32_t Wh = bb_ + OFF_WH, Wl = bb_ + OFF_WL;

#pragma unroll
        for (int kk = 0; kk < 4; kk++) {       // 4 x k16 per stage
            uint32_t ah[2][4], al[2][4];
#pragma unroll
            for (int mi = 0; mi < 2; mi++) {
                const int krow  = kk * 16 + l7 + l16 * 8;
                const int mbyte = (warp_m * 32 + mi * 16) * 2 + l8 * 16;
                const uint32_t off = aswz(krow, mbyte);
                LDSM4T(ah[mi], Ah + off);
                LDSM4T(al[mi], Al + off);
            }
#pragma unroll
            for (int ni = 0; ni < 5; ni++) {
                const int n = warp_n * 40 + ni * 8 + l7;
                const uint32_t off = SWZ((uint32_t)n * 128 + (uint32_t)kk * 32 + (uint32_t)l8 * 16);
                uint32_t bh[2], bl[2];
                LDSM2(bh, Wh + off);
                LDSM2(bl, Wl + off);
                MMA16816(acc[0][ni], ah[0], bh);
                MMA16816(acc[1][ni], ah[1], bh);
                MMA16816(acc[0][ni], ah[0], bl);
                MMA16816(acc[1][ni], ah[1], bl);
                MMA16816(acc[0][ni], al[0], bh);
                MMA16816(acc[1][ni], al[1], bh);
            }
        }
        __syncthreads();
    }

    // ---- epilogue: bias + scattered stores (L2 merges sectors) ----
    const int g  = lane >> 2;
    const int t4 = lane & 3;
    const size_t row_base = (size_t)b * ROWS_PER_B + moff;
#pragma unroll
    for (int mi = 0; mi < 2; mi++) {
#pragma unroll
        for (int rr = 0; rr < 2; rr++) {
            const int m = m_base + warp_m * 32 + mi * 16 + g + rr * 8;
            if (m < M) {
                const size_t row = (row_base + m) * OUT_COLS;
#pragma unroll
                for (int ni = 0; ni < 5; ni++) {
                    const int c0 = warp_n * 40 + ni * 8 + t4 * 2;
#pragma unroll
                    for (int e = 0; e < 2; e++) {
                        const int c = c0 + e;
                        const float v = acc[mi][ni][rr * 2 + e] + biasS[c];
                        if (type == 0) {
                            out[row + 1 + c] = v;
                        } else {
                            if (c == 0)      out[row]          = v;
                            else if (c < 65) out[row + 80 + c] = v;
                        }
                    }
                }
            }
        }
    }
}

// DFL softmax-expectation + anchor box decode, reading reg cols back via L2.
__global__ void dfl_kernel(float* __restrict__ out, int total_rows)
{
    const int gid = blockIdx.x * blockDim.x + threadIdx.x;
    if (gid >= total_rows * 4) return;
    const int side = gid & 3;
    const int row  = gid >> 2;
    const int mg   = row % ROWS_PER_B;

    int Wd, mloc; float stride_f;
    if (mg < 6400)      { Wd = 80; stride_f = 8.0f;  mloc = mg; }
    else if (mg < 8000) { Wd = 40; stride_f = 16.0f; mloc = mg - 6400; }
    else                { Wd = 20; stride_f = 32.0f; mloc = mg - 8000; }

    const float* p = out + (size_t)row * OUT_COLS + 81 + side * 16;
    float v[16], vmax = -1e30f;
#pragma unroll
    for (int r = 0; r < 16; r++) { v[r] = p[r]; vmax = fmaxf(vmax, v[r]); }
    float sum = 0.0f, dot = 0.0f;
#pragma unroll
    for (int r = 0; r < 16; r++) {
        const float e = __expf(v[r] - vmax);
        sum += e;
        dot = fmaf(e, (16.0f / 15.0f) * (float)r, dot);   // proj = linspace(0,16,16)
    }
    const float d  = dot / sum;
    const int   x  = mloc % Wd;
    const int   y  = mloc / Wd;
    const float ax = ((float)x + 0.5f) * stride_f;
    const float ay = ((float)y + 0.5f) * stride_f;
    float coord;
    if      (side == 0) coord = ax - d * stride_f;
    else if (side == 1) coord = ay - d * stride_f;
    else if (side == 2) coord = ax + d * stride_f;
    else                coord = ay + d * stride_f;
    out[(size_t)row * OUT_COLS + 145 + side] = coord;
}

extern "C" void kernel_launch(void* const* d_in, const int* in_sizes, int n_in,
                              void* d_out, int out_size)
{
    // Feature ordering: dict-interleaved (cls0,reg0,...) vs signature (cls0..2,reg0..2),
    // disambiguated by size (interleaved <=> sizes[0]==sizes[1]).
    const bool interleaved = (in_sizes[1] == in_sizes[0]);
    AllP ap;
    for (int l = 0; l < 3; l++) {
        const float* cf, *rf;
        if (interleaved) { cf = (const float*)d_in[2 * l]; rf = (const float*)d_in[2 * l + 1]; }
        else             { cf = (const float*)d_in[l];     rf = (const float*)d_in[3 + l]; }
        const float* obj_w = (const float*)d_in[6 + 6 * l + 0];
        const float* obj_b = (const float*)d_in[6 + 6 * l + 1];
        const float* cls_w = (const float*)d_in[6 + 6 * l + 2];
        const float* cls_b = (const float*)d_in[6 + 6 * l + 3];
        const float* reg_w = (const float*)d_in[6 + 6 * l + 4];
        const float* reg_b = (const float*)d_in[6 + 6 * l + 5];
        ap.p[0][l] = { cf, cls_w, nullptr, cls_b, nullptr };   // cls
        ap.p[1][l] = { rf, obj_w, reg_w,   obj_b, reg_b  };    // obj+reg
    }

    float* out = (float*)d_out;
    cudaFuncSetAttribute(hmma_kernel, cudaFuncAttributeMaxDynamicSharedMemorySize, SMEM_TOTAL);

    wconv_kernel<<<6, NT>>>(ap);                 // pre-convert W (bf16 hi/lo) once

    dim3 grid(67, 16, 2);   // 50+13+4 m-tiles, 16 batch, {cls, reg}
    hmma_kernel<<<grid, NT, SMEM_TOTAL>>>(ap, out);

    const int total_rows = 16 * ROWS_PER_B;   // 134400
    const int nthr = total_rows * 4;
    dfl_kernel<<<(nthr + 255) / 256, 256>>>(out, total_rows);
}